// round 15
// baseline (speedup 1.0000x reference)
#include <cuda_runtime.h>
#include <cuda_fp16.h>

// APPNP: h_{k+1} = (1-a) * Dinv(A+I)Dinv * h_k + a * x,  K=5, a=0.8
// g = dinv .* h stored FP16, rows padded to 128B (8 uint4 chunks, 6 used).
// VECTORIZED gather: lane = (edge slot el=lane>>3, chunk c=lane&7, act=c<6);
// each active lane LDG.128s 16B of its edge's row -> 1 gather LDG per 4 edges.
// fp16 HADD2 accumulation in-lane; one fp32 shfl_xor(8,16) reduce per node.

#define NN 100000
#define EE 1600000
#define CH 6                // used 16B chunks per row (48 halfs = 96B)
#define RS 8                // uint4 stride per row (128B padded)
#define CSR_CAP (EE + 3 * NN + 4)
#define ALPHA 0.8f

// ---------------- device scratch (static, no allocation) ----------------
__device__ int   g_ecount[NN];    // zero at every kernel_launch entry (invariant)
__device__ int   g_total;         // zero at entry (invariant)
__device__ float g_dinv[NN];
__device__ int   g_colstart[NN];
__device__ int   g_colend[NN];    // padded end (multiple-of-4 segment)
__device__ int   g_rank[EE];
__device__ int4  g_csr4[CSR_CAP / 4 + 1];
__device__ uint4 g_bufA[(NN + 1) * RS];   // fp16 rows; row NN = permanent zeros
__device__ uint4 g_bufB[(NN + 1) * RS];   // (never written)

// ---------------- preprocessing ----------------
__global__ void k_hist(const int* __restrict__ col) {
    int e = blockIdx.x * blockDim.x + threadIdx.x;
    if (e < EE) g_rank[e] = atomicAdd(&g_ecount[col[e]], 1);
}

__global__ void k_alloc() {
    int v = blockIdx.x * blockDim.x + threadIdx.x;
    if (v < NN) {
        int c  = g_ecount[v];
        int cp = (c + 3) & ~3;
        int p  = atomicAdd(&g_total, cp);       // g_total starts 0 -> p 4-aligned
        g_colstart[v] = p;
        g_colend[v]   = p + cp;
        int* csr = (int*)g_csr4;
        for (int j = c; j < cp; j++) csr[p + j] = NN;   // zero-row padding
        g_dinv[v] = rsqrtf((float)(c + 1));     // +1 self loop
    }
}

// scatter (atomic-free) + g0 = fp16(dinv.*x) + restore zero-invariant
__global__ void k_scatter_fused(const int* __restrict__ row, const int* __restrict__ col,
                                const float2* __restrict__ x2, __half2* __restrict__ g0) {
    int t = blockIdx.x * blockDim.x + threadIdx.x;
    if (t < EE) {
        int p = g_colstart[col[t]] + g_rank[t];
        ((int*)g_csr4)[p] = row[t];
    }
    if (t < NN * 24) {                  // 24 half2 chunks per row
        int v = t / 24, c = t % 24;
        float s = g_dinv[v];
        float2 a = x2[t];
        g0[v * 32 + c] = __floats2half2_rn(a.x * s, a.y * s);   // 32 half2 = 128B stride
    }
    if (t < NN) g_ecount[t] = 0;        // ecount dead after k_alloc; re-zero
    if (t == 0) g_total = 0;
}

// ---------------- propagation ----------------
// Warp per node. el = lane>>3 (4 edge slots), c = lane&7 (16B chunk), act = c<6.
template <bool WRITE_H>
__global__ void __launch_bounds__(256, 8) k_propagate(const uint4* __restrict__ gin4,
                                                      const float4* __restrict__ x4,
                                                      void* __restrict__ gout_) {
    int v    = (blockIdx.x * blockDim.x + threadIdx.x) >> 5;
    int lane = threadIdx.x & 31;
    if (v >= NN) return;

    int el = lane >> 3;
    int c  = lane & 7;
    bool act = (c < CH);

    int b   = g_colstart[v];
    int end = g_colend[v];                 // multiple-of-4 segment, no tail

    __half2 z = __floats2half2_rn(0.f, 0.f);
    __half2 acc0 = z, acc1 = z, acc2 = z, acc3 = z;

    for (; b < end; b += 4) {
        int4 r4 = __ldg(&g_csr4[b >> 2]);  // uniform: 4 edge indices
        int r = (el == 0) ? r4.x : (el == 1) ? r4.y : (el == 2) ? r4.z : r4.w;
        if (act) {
            uint4 u = __ldg(&gin4[r * RS + c]);   // 16B of this edge's row
            acc0 = __hadd2(acc0, *(__half2*)&u.x);
            acc1 = __hadd2(acc1, *(__half2*)&u.y);
            acc2 = __hadd2(acc2, *(__half2*)&u.z);
            acc3 = __hadd2(acc3, *(__half2*)&u.w);
        }
    }

    // to fp32 and reduce across the 4 edge slots (lane bits 3,4)
    float f[8];
    {
        float2 p;
        p = __half22float2(acc0); f[0] = p.x; f[1] = p.y;
        p = __half22float2(acc1); f[2] = p.x; f[3] = p.y;
        p = __half22float2(acc2); f[4] = p.x; f[5] = p.y;
        p = __half22float2(acc3); f[6] = p.x; f[7] = p.y;
    }
    #pragma unroll
    for (int k = 0; k < 8; k++) {
        f[k] += __shfl_xor_sync(0xffffffffu, f[k], 8);
        f[k] += __shfl_xor_sync(0xffffffffu, f[k], 16);
    }

    // lanes 0..5 own chunk `lane` (dims 8*lane .. 8*lane+7)
    if (lane < CH) {
        float di = g_dinv[v];

        uint4 sv = __ldg(&gin4[v * RS + lane]);   // self loop chunk
        float gs[8];
        {
            float2 p;
            p = __half22float2(*(__half2*)&sv.x); gs[0] = p.x; gs[1] = p.y;
            p = __half22float2(*(__half2*)&sv.y); gs[2] = p.x; gs[3] = p.y;
            p = __half22float2(*(__half2*)&sv.z); gs[4] = p.x; gs[5] = p.y;
            p = __half22float2(*(__half2*)&sv.w); gs[6] = p.x; gs[7] = p.y;
        }

        float4 xa = __ldg(&x4[v * 12 + 2 * lane]);
        float4 xb = __ldg(&x4[v * 12 + 2 * lane + 1]);
        float xs[8] = {xa.x, xa.y, xa.z, xa.w, xb.x, xb.y, xb.z, xb.w};

        float h[8];
        #pragma unroll
        for (int j = 0; j < 8; j++)
            h[j] = (1.0f - ALPHA) * (di * (f[j] + gs[j])) + ALPHA * xs[j];

        if (WRITE_H) {
            float4* out = (float4*)gout_;
            out[v * 12 + 2 * lane]     = make_float4(h[0], h[1], h[2], h[3]);
            out[v * 12 + 2 * lane + 1] = make_float4(h[4], h[5], h[6], h[7]);
        } else {
            uint4 o;   // store g = dinv*h as fp16
            *(__half2*)&o.x = __floats2half2_rn(h[0] * di, h[1] * di);
            *(__half2*)&o.y = __floats2half2_rn(h[2] * di, h[3] * di);
            *(__half2*)&o.z = __floats2half2_rn(h[4] * di, h[5] * di);
            *(__half2*)&o.w = __floats2half2_rn(h[6] * di, h[7] * di);
            ((uint4*)gout_)[v * RS + lane] = o;
        }
    }
}

// ---------------- launch ----------------
extern "C" void kernel_launch(void* const* d_in, const int* in_sizes, int n_in,
                              void* d_out, int out_size) {
    const float2* x2 = (const float2*)d_in[0];
    const float4* x4 = (const float4*)d_in[0];
    const int*    ei = (const int*)d_in[1];
    const int* row = ei;          // edge_index[0]
    const int* col = ei + EE;     // edge_index[1]

    uint4 *pA, *pB;
    cudaGetSymbolAddress((void**)&pA, g_bufA);
    cudaGetSymbolAddress((void**)&pB, g_bufB);

    k_hist<<<(EE + 255) / 256, 256>>>(col);                        // launch 1
    k_alloc<<<(NN + 255) / 256, 256>>>();                          // launch 2
    const int FT = NN * 24;
    k_scatter_fused<<<(FT + 255) / 256, 256>>>(row, col, x2, (__half2*)pA);  // launch 3

    const int PBLK = 256;                       // 8 warps = 8 nodes per block
    const int PGRID = (NN + 7) / 8;             // 12500
    k_propagate<false><<<PGRID, PBLK>>>(pA, x4, pB);    // launch 4 <- profiled
    k_propagate<false><<<PGRID, PBLK>>>(pB, x4, pA);
    k_propagate<false><<<PGRID, PBLK>>>(pA, x4, pB);
    k_propagate<false><<<PGRID, PBLK>>>(pB, x4, pA);
    k_propagate<true ><<<PGRID, PBLK>>>(pA, x4, d_out); // step 5 -> h (fp32)
}

// round 16
// speedup vs baseline: 1.2062x; 1.2062x over previous
#include <cuda_runtime.h>
#include <cuda_fp16.h>

// APPNP: h_{k+1} = (1-a) * Dinv(A+I)Dinv * h_k + a * x,  K=5, a=0.8
// g = dinv .* h stored FP16, rows padded to 128B (1 L1 wavefront per warp-wide
// row gather). Dim-parallel: lane<24 owns one half2 chunk; no reduction.
// Per-quad fp16 adder tree (3 HADD2 + cvt + 2 FADD).
// PERSISTENT propagate: one fully-resident wave (148x7 blocks), each warp
// grid-strides over ~12 nodes -> no wave transitions, no tail wave.

#define NN 100000
#define EE 1600000
#define F2 24               // chunks per row (48 dims / 2)
#define GS 32               // half2 stride per fp16 row (128B padded)
#define CSR_CAP (EE + 3 * NN + 4)
#define ALPHA 0.8f
#define PGRID 1036          // 148 SMs x 7 resident blocks
#define PBLK  256

// ---------------- device scratch (static, no allocation) ----------------
__device__ int     g_ecount[NN];    // zero at every kernel_launch entry (invariant)
__device__ int     g_total;         // zero at entry (invariant)
__device__ float   g_dinv[NN];
__device__ int     g_colstart[NN];
__device__ int     g_colend[NN];    // padded end (multiple-of-4 segment)
__device__ int     g_rank[EE];
__device__ int4    g_csr4[CSR_CAP / 4 + 1];
__device__ __half2 g_bufA[(NN + 1) * GS];   // row NN = permanent zeros
__device__ __half2 g_bufB[(NN + 1) * GS];   // (never written)

// ---------------- preprocessing ----------------
__global__ void k_hist(const int* __restrict__ col) {
    int e = blockIdx.x * blockDim.x + threadIdx.x;
    if (e < EE) g_rank[e] = atomicAdd(&g_ecount[col[e]], 1);
}

__global__ void k_alloc() {
    int v = blockIdx.x * blockDim.x + threadIdx.x;
    if (v < NN) {
        int c  = g_ecount[v];
        int cp = (c + 3) & ~3;
        int p  = atomicAdd(&g_total, cp);       // g_total starts 0 -> p 4-aligned
        g_colstart[v] = p;
        g_colend[v]   = p + cp;
        int* csr = (int*)g_csr4;
        for (int j = c; j < cp; j++) csr[p + j] = NN;   // zero-row padding
        g_dinv[v] = rsqrtf((float)(c + 1));     // +1 self loop
    }
}

// scatter (atomic-free) + g0 = fp16(dinv.*x) + restore zero-invariant
__global__ void k_scatter_fused(const int* __restrict__ row, const int* __restrict__ col,
                                const float2* __restrict__ x2, __half2* __restrict__ g0) {
    int t = blockIdx.x * blockDim.x + threadIdx.x;
    if (t < EE) {
        int p = g_colstart[col[t]] + g_rank[t];
        ((int*)g_csr4)[p] = row[t];
    }
    if (t < NN * F2) {
        int v = t / F2, c = t % F2;
        float s = g_dinv[v];
        float2 a = x2[t];
        g0[v * GS + c] = __floats2half2_rn(a.x * s, a.y * s);
    }
    if (t < NN) g_ecount[t] = 0;       // ecount dead after k_alloc; re-zero
    if (t == 0) g_total = 0;
}

// ---------------- propagation ----------------
// Persistent: warp strides over nodes. lane<24 owns chunk `lane` of each row.
template <bool WRITE_H>
__global__ void __launch_bounds__(PBLK, 7) k_propagate(const __half2* __restrict__ gin,
                                                       const float2* __restrict__ x2,
                                                       void* __restrict__ gout_) {
    int gwarp  = (blockIdx.x * PBLK + threadIdx.x) >> 5;
    int nwarps = (PGRID * PBLK) >> 5;              // 8288
    int lane   = threadIdx.x & 31;
    bool act   = (lane < F2);

    for (int v = gwarp; v < NN; v += nwarps) {
        int b   = g_colstart[v];
        int end = g_colend[v];                     // multiple-of-4 segment

        float2 acc = make_float2(0.f, 0.f);

        for (; b < end; b += 4) {
            int4 r = __ldg(&g_csr4[b >> 2]);       // 4 edge indices, 1 wavefront
            if (act) {
                __half2 u0 = __ldg(&gin[r.x * GS + lane]);
                __half2 u1 = __ldg(&gin[r.y * GS + lane]);
                __half2 u2 = __ldg(&gin[r.z * GS + lane]);
                __half2 u3 = __ldg(&gin[r.w * GS + lane]);
                __half2 s  = __hadd2(__hadd2(u0, u1), __hadd2(u2, u3));
                float2  f  = __half22float2(s);
                acc.x += f.x;
                acc.y += f.y;
            }
        }

        if (act) {
            float di  = g_dinv[v];
            float2 gv = __half22float2(__ldg(&gin[v * GS + lane]));   // self loop
            float2 xx = __ldg(&x2[v * F2 + lane]);

            float2 h;
            h.x = (1.0f - ALPHA) * (di * (acc.x + gv.x)) + ALPHA * xx.x;
            h.y = (1.0f - ALPHA) * (di * (acc.y + gv.y)) + ALPHA * xx.y;

            if (WRITE_H) {
                ((float2*)gout_)[v * F2 + lane] = h;
            } else {   // store g = dinv*h as fp16 for next step
                ((__half2*)gout_)[v * GS + lane] = __floats2half2_rn(h.x * di, h.y * di);
            }
        }
    }
}

// ---------------- launch ----------------
extern "C" void kernel_launch(void* const* d_in, const int* in_sizes, int n_in,
                              void* d_out, int out_size) {
    const float2* x2 = (const float2*)d_in[0];
    const int*    ei = (const int*)d_in[1];
    const int* row = ei;          // edge_index[0]
    const int* col = ei + EE;     // edge_index[1]

    __half2 *pA, *pB;
    cudaGetSymbolAddress((void**)&pA, g_bufA);
    cudaGetSymbolAddress((void**)&pB, g_bufB);

    k_hist<<<(EE + 255) / 256, 256>>>(col);                        // launch 1
    k_alloc<<<(NN + 255) / 256, 256>>>();                          // launch 2
    const int FT = NN * F2;
    k_scatter_fused<<<(FT + 255) / 256, 256>>>(row, col, x2, pA);  // launch 3

    k_propagate<false><<<PGRID, PBLK>>>(pA, x2, pB);    // launch 4 <- profiled
    k_propagate<false><<<PGRID, PBLK>>>(pB, x2, pA);
    k_propagate<false><<<PGRID, PBLK>>>(pA, x2, pB);
    k_propagate<false><<<PGRID, PBLK>>>(pB, x2, pA);
    k_propagate<true ><<<PGRID, PBLK>>>(pA, x2, d_out); // step 5 -> h (fp32)
}